// round 2
// baseline (speedup 1.0000x reference)
#include <cuda_runtime.h>
#include <math.h>

#define BATCH 8
#define NPTS  256
#define CH    32
#define MODES 16
#define NLAY  4
#define HID   128

// ---------------- scratch (static device globals; no allocations) ----------------
__device__ float  g_h[BATCH*CH*NPTS*NPTS];          // 64 MB, [b][c][x][y]
__device__ float2 g_A[BATCH*MODES*CH*NPTS];         // fwd y-DFT, [b][ky][c][x]
__device__ float2 g_T2[BATCH*NPTS*MODES*CH];        // after inv x-DFT, [b][x][ky][o]
__device__ float2 g_Wp[NLAY*MODES*MODES*CH*CH];     // repacked spec weights [l][ky][kx][i][o]
__device__ float  g_ctab[MODES*NPTS];               // cos(2*pi*k*y/256)  [k][y]
__device__ float  g_stab[MODES*NPTS];               // sin                [k][y]
__device__ float  g_ctT[NPTS*MODES];                // transposed [x][k]
__device__ float  g_stT[NPTS*MODES];
__device__ float  g_tabT[NPTS*32];                  // [y][m]: m<16 cos, m>=16 -sin

// Branch-free erf-based GELU (Abramowitz-Stegun 7.1.26, |err| < 2e-7)
__device__ __forceinline__ float gelu_f(float v) {
    float x = fabsf(v) * 0.7071067811865475f;
    float t = __fdividef(1.0f, fmaf(0.3275911f, x, 1.0f));
    float p = t * fmaf(t, fmaf(t, fmaf(t, fmaf(t, 1.061405429f, -1.453152027f),
                 1.421413741f), -0.284496736f), 0.254829592f);
    float erfax = 1.0f - p * __expf(-x * x);
    float erfv = copysignf(erfax, v);
    return 0.5f * v * (1.0f + erfv);
}

// ---------------- tables (exact mod-256 angle reduction) ----------------
__global__ void k_tables() {
    int k = blockIdx.x;          // 0..15
    int y = threadIdx.x;         // 0..255
    int p = (k * y) & 255;
    float ang = (float)p * 0.024543692606170259f;  // 2*pi/256
    float s, c;
    sincosf(ang, &s, &c);
    g_ctab[k*NPTS+y] = c;   g_stab[k*NPTS+y] = s;
    g_ctT[y*MODES+k] = c;   g_stT[y*MODES+k] = s;
    g_tabT[y*32+k] = c;     g_tabT[y*32+16+k] = -s;
}

// ---------------- repack spectral weights [l][i][o][kx][ky] -> [l][ky][kx][i][o] ----------------
__global__ void k_repack(const float* __restrict__ wr, const float* __restrict__ wi) {
    int blk = blockIdx.x;          // 0..127 = l*32 + i
    int l = blk >> 5, i = blk & 31;
    const float* wrb = wr + (size_t)blk * CH * MODES * MODES;
    const float* wib = wi + (size_t)blk * CH * MODES * MODES;
    for (int idx = threadIdx.x; idx < MODES*MODES*CH; idx += blockDim.x) {
        int o  = idx & 31;
        int kx = (idx >> 5) & 15;
        int ky = idx >> 9;
        int s  = o*(MODES*MODES) + kx*MODES + ky;
        g_Wp[(((size_t)(l*MODES+ky)*MODES+kx)*CH + i)*CH + o] = make_float2(wrb[s], wib[s]);
    }
}

// ---------------- lifting: (bc,x,y) -> h[b][c][x][y] ----------------
__global__ void k_lift(const float* __restrict__ bc, const float* __restrict__ xin,
                       const float* __restrict__ yin, const float* __restrict__ mw,
                       const float* __restrict__ mb) {
    int blk = blockIdx.x;                 // b*256 + xi
    int b = blk >> 8, xi = blk & 255;
    int y = threadIdx.x;                  // 256
    float b0 = bc[b*3+0], b1 = bc[b*3+1], b2 = bc[b*3+2];
    float xv = xin[(b*NPTS+xi)*NPTS + y];
    float yv = yin[(b*NPTS+xi)*NPTS + y];
    #pragma unroll
    for (int c = 0; c < CH; c++) {
        float h = mb[c] + b0*mw[c] + b1*mw[32+c] + b2*mw[64+c] + xv*mw[96+c] + yv*mw[128+c];
        g_h[((size_t)(b*CH+c)*NPTS + xi)*NPTS + y] = h;
    }
}

// ---------------- forward y-DFT: h -> A (16 complex modes, no scale) ----------------
// block = (bcIdx, x-tile of 16); 128 threads = 4 x-groups * 32 "modes" (16 re + 16 im)
__global__ __launch_bounds__(128) void k_fwd() {
    int tid = threadIdx.x;
    int blk = blockIdx.x;              // BATCH*CH*16
    int xt = blk & 15;
    int bcIdx = blk >> 4;              // b*32+c
    int m = tid & 31, xg = tid >> 5;

    const float* tab = g_tabT;
    const float4* hrow = (const float4*)(g_h + ((size_t)bcIdx*NPTS + xt*16 + xg*4)*NPTS);
    float a0 = 0.f, a1 = 0.f, a2 = 0.f, a3 = 0.f;
    #pragma unroll 4
    for (int yc = 0; yc < 64; yc++) {
        float t0 = tab[(yc*4+0)*32+m];
        float t1 = tab[(yc*4+1)*32+m];
        float t2 = tab[(yc*4+2)*32+m];
        float t3 = tab[(yc*4+3)*32+m];
        float4 v;
        v = hrow[yc];        a0 += v.x*t0 + v.y*t1 + v.z*t2 + v.w*t3;
        v = hrow[64+yc];     a1 += v.x*t0 + v.y*t1 + v.z*t2 + v.w*t3;
        v = hrow[128+yc];    a2 += v.x*t0 + v.y*t1 + v.z*t2 + v.w*t3;
        v = hrow[192+yc];    a3 += v.x*t0 + v.y*t1 + v.z*t2 + v.w*t3;
    }
    int b = bcIdx >> 5, c = bcIdx & 31;
    int ky = m & 15, comp = m >> 4;     // m<16: re (cos table), m>=16: im (-sin table)
    float* Ab = (float*)g_A;
    size_t base = ((size_t)(b*MODES+ky)*CH + c)*NPTS + xt*16 + xg*4;
    Ab[(base+0)*2 + comp] = a0;
    Ab[(base+1)*2 + comp] = a1;
    Ab[(base+2)*2 + comp] = a2;
    Ab[(base+3)*2 + comp] = a3;
}

// ---------------- x-DFT + mode mixing + inverse x-DFT ----------------
// block = (b, ky): 128 blocks, 512 threads
__global__ __launch_bounds__(512) void k_spec(int layer) {
    __shared__ float2 Hft[CH*MODES];     //  4 KB [i][kx]
    __shared__ float  Tmr[CH*17];        // padded [o][kx]
    __shared__ float  Tmi[CH*17];
    int tid = threadIdx.x;               // 512
    int b = blockIdx.x >> 4, ky = blockIdx.x & 15;

    // forward x-DFT: Hft[c][kx] = (1/256) * sum_x A[c][x] * e^{-i 2pi kx x/256}
    {
        int c = tid >> 4, kx = tid & 15;
        const float2* Arow = g_A + ((size_t)(b*MODES+ky)*CH + c)*NPTS;
        float ar = 0.f, ai = 0.f;
        #pragma unroll 4
        for (int x = 0; x < 256; x++) {
            float2 a = Arow[x];
            float cc = g_ctT[x*16+kx], sv = g_stT[x*16+kx];
            ar += a.x*cc + a.y*sv;
            ai += a.y*cc - a.x*sv;
        }
        Hft[c*16+kx] = make_float2(ar*(1.0f/256.0f), ai*(1.0f/256.0f));
    }
    __syncthreads();

    // mode mixing: T[o][kx] = sum_i Hft[i][kx] * (wr + i*wi)[i][o]
    {
        int kx = tid >> 5, o = tid & 31;
        const float2* W = g_Wp + ((size_t)((layer*MODES+ky)*MODES + kx)*CH)*CH;
        float tr = 0.f, ti = 0.f;
        #pragma unroll 8
        for (int i = 0; i < CH; i++) {
            float2 hh = Hft[i*16+kx];
            float2 w = W[i*32+o];
            tr += hh.x*w.x - hh.y*w.y;
            ti += hh.x*w.y + hh.y*w.x;
        }
        Tmr[o*17+kx] = tr;
        Tmi[o*17+kx] = ti;
    }
    __syncthreads();

    // inverse x-DFT (hermitian-y doubling + inverse 1/256 folded in):
    // T2[o][x] = scale * sum_kx T[o][kx] * e^{+i 2pi kx x/256}
    {
        int xg = tid >> 5, o = tid & 31;
        float Tr[16], Ti[16];
        #pragma unroll
        for (int k = 0; k < 16; k++) { Tr[k] = Tmr[o*17+k]; Ti[k] = Tmi[o*17+k]; }
        float scale = (ky == 0) ? (1.0f/256.0f) : (2.0f/256.0f);
        for (int j = 0; j < 16; j++) {
            int x = xg*16 + j;
            float br = 0.f, bi = 0.f;
            #pragma unroll
            for (int k = 0; k < 16; k++) {
                float cc = g_ctT[x*16+k], sv = g_stT[x*16+k];
                br += Tr[k]*cc - Ti[k]*sv;
                bi += Tr[k]*sv + Ti[k]*cc;
            }
            g_T2[((size_t)(b*NPTS+x)*MODES + ky)*CH + o] = make_float2(br*scale, bi*scale);
        }
    }
}

// ---------------- combine: h = h + gelu(inv-y-DFT(T2) + pointwise(h) + bias) ----------------
// block = (b, x), 256 threads (thread = y); in-place (h cached in registers first)
__global__ __launch_bounds__(256) void k_layer(const float* __restrict__ pww,
                                               const float* __restrict__ pwb, int layer) {
    __shared__ float2 T2s[MODES*CH];   // [ky][o], 4 KB
    __shared__ float  ws[CH*CH];       // [o][i],  4 KB
    __shared__ float  pbs[CH];
    int tid = threadIdx.x;             // 256
    int b = blockIdx.x >> 8, x = blockIdx.x & 255;

    {
        const float4* src = (const float4*)(g_T2 + (size_t)(b*NPTS + x)*MODES*CH);
        float4* dst = (float4*)T2s;
        dst[tid] = src[tid];           // 512 float2 = 256 float4
    }
    for (int i = tid; i < CH*CH; i += 256) ws[i] = pww[layer*CH*CH + i];
    if (tid < CH) pbs[tid] = pwb[layer*CH + tid];

    int y = tid;
    float hreg[CH];
    #pragma unroll
    for (int i = 0; i < CH; i++) hreg[i] = g_h[((size_t)(b*CH+i)*NPTS + x)*NPTS + y];
    float cr[16], snr[16];
    #pragma unroll
    for (int k = 0; k < 16; k++) { cr[k] = g_ctab[k*NPTS+y]; snr[k] = -g_stab[k*NPTS+y]; }
    __syncthreads();

    #pragma unroll 4
    for (int o = 0; o < CH; o++) {
        float acc = pbs[o];
        #pragma unroll
        for (int i = 0; i < CH; i++) acc += hreg[i] * ws[o*32+i];
        #pragma unroll
        for (int k = 0; k < 16; k++) {
            float2 t2 = T2s[k*32+o];
            acc += t2.x*cr[k] + t2.y*snr[k];
        }
        g_h[((size_t)(b*CH+o)*NPTS + x)*NPTS + y] = hreg[o] + gelu_f(acc);
    }
}

// ---------------- decoders: 3x (32 -> 32 -> 128 -> 1), one point/thread ----------------
__global__ __launch_bounds__(256) void k_dec(
        const float* __restrict__ w1, const float* __restrict__ b1,
        const float* __restrict__ w2, const float* __restrict__ b2,
        const float* __restrict__ w3, const float* __restrict__ b3,
        float* __restrict__ out) {
    __shared__ float W1t[CH*CH];     // [j][i], 4 KB
    __shared__ float W2t[HID*CH];    // [j][i], 16 KB
    __shared__ float W3s[HID];
    __shared__ float B1s[CH];
    __shared__ float B2s[HID];
    int tid = threadIdx.x;
    int b = blockIdx.x >> 8, x = blockIdx.x & 255;
    int y = tid;

    float hreg[CH];
    #pragma unroll
    for (int i = 0; i < CH; i++) hreg[i] = g_h[((size_t)(b*CH+i)*NPTS + x)*NPTS + y];

    float res[3];
    for (int d = 0; d < 3; d++) {
        __syncthreads();
        for (int idx = tid; idx < CH*CH; idx += 256) {
            int j = idx >> 5, i = idx & 31;
            W1t[idx] = w1[d*CH*CH + i*CH + j];       // transpose to [j][i]
        }
        for (int idx = tid; idx < HID*CH; idx += 256) {
            int j = idx >> 5, i = idx & 31;
            W2t[idx] = w2[d*CH*HID + i*HID + j];     // transpose to [j][i]
        }
        if (tid < HID) { W3s[tid] = w3[d*HID + tid]; B2s[tid] = b2[d*HID + tid]; }
        if (tid < CH)  B1s[tid] = b1[d*CH + tid];
        __syncthreads();

        float z1[CH];
        #pragma unroll
        for (int j = 0; j < CH; j++) {
            float a = B1s[j];
            #pragma unroll
            for (int i = 0; i < CH; i++) a += hreg[i] * W1t[j*CH+i];
            z1[j] = gelu_f(a);
        }
        float o = b3[d];
        #pragma unroll 4
        for (int j = 0; j < HID; j++) {
            float a = B2s[j];
            #pragma unroll
            for (int i = 0; i < CH; i++) a += z1[i] * W2t[j*CH+i];
            o += W3s[j] * gelu_f(a);
        }
        res[d] = o;
    }
    size_t p = ((size_t)(b*NPTS + x))*NPTS + y;
    out[p*3+0] = res[0];
    out[p*3+1] = res[1];
    out[p*3+2] = res[2];
}

extern "C" void kernel_launch(void* const* d_in, const int* in_sizes, int n_in,
                              void* d_out, int out_size) {
    const float* bc      = (const float*)d_in[0];
    const float* xin     = (const float*)d_in[1];
    const float* yin     = (const float*)d_in[2];
    const float* mlp1_w  = (const float*)d_in[3];
    const float* mlp1_b  = (const float*)d_in[4];
    const float* spec_wr = (const float*)d_in[5];
    const float* spec_wi = (const float*)d_in[6];
    const float* pw_w    = (const float*)d_in[7];
    const float* pw_b    = (const float*)d_in[8];
    const float* dec_w1  = (const float*)d_in[9];
    const float* dec_b1  = (const float*)d_in[10];
    const float* dec_w2  = (const float*)d_in[11];
    const float* dec_b2  = (const float*)d_in[12];
    const float* dec_w3  = (const float*)d_in[13];
    const float* dec_b3  = (const float*)d_in[14];
    float* out = (float*)d_out;

    k_tables<<<16, 256>>>();
    k_repack<<<NLAY*CH, 256>>>(spec_wr, spec_wi);
    k_lift<<<BATCH*NPTS, 256>>>(bc, xin, yin, mlp1_w, mlp1_b);
    for (int l = 0; l < NLAY; l++) {
        k_fwd<<<BATCH*CH*16, 128>>>();
        k_spec<<<BATCH*MODES, 512>>>(l);
        k_layer<<<BATCH*NPTS, 256>>>(pw_w, pw_b, l);
    }
    k_dec<<<BATCH*NPTS, 256>>>(dec_w1, dec_b1, dec_w2, dec_b2, dec_w3, dec_b3, out);
}

// round 3
// speedup vs baseline: 1.0103x; 1.0103x over previous
#include <cuda_runtime.h>
#include <math.h>

#define BATCH 8
#define NPTS  256
#define CH    32
#define MODES 16
#define NLAY  4
#define HID   128

typedef unsigned long long u64;
typedef ulonglong2 u64x2;

// ---------------- packed f32x2 helpers (sm_100+) ----------------
__device__ __forceinline__ u64 pk(float lo, float hi) {
    u64 r; asm("mov.b64 %0, {%1, %2};" : "=l"(r) : "f"(lo), "f"(hi)); return r;
}
__device__ __forceinline__ void upk(u64 v, float& lo, float& hi) {
    asm("mov.b64 {%0, %1}, %2;" : "=f"(lo), "=f"(hi) : "l"(v));
}
__device__ __forceinline__ u64 fma2(u64 a, u64 b, u64 c) {
    u64 d; asm("fma.rn.f32x2 %0, %1, %2, %3;" : "=l"(d) : "l"(a), "l"(b), "l"(c)); return d;
}

// ---------------- scratch (static device globals; no allocations) ----------------
__device__ float  g_h[BATCH*CH*NPTS*NPTS];          // 64 MB, [b][c][x][y]
__device__ float2 g_A[BATCH*MODES*CH*NPTS];         // fwd y-DFT, [b][ky][c][x]
__device__ float2 g_T2[BATCH*NPTS*MODES*CH];        // after inv x-DFT, [b][x][ky][o]
__device__ float2 g_Wp[NLAY*MODES*MODES*CH*CH];     // repacked spec weights [l][ky][kx][i][o]
__device__ float  g_ctab[MODES*NPTS];               // cos(2*pi*k*y/256)  [k][y]
__device__ float  g_stab[MODES*NPTS];               // sin                [k][y]
__device__ float  g_ctT[NPTS*MODES];                // transposed [x][k]
__device__ float  g_stT[NPTS*MODES];

// Branch-free erf-based GELU (Abramowitz-Stegun 7.1.26, |err| < 2e-7)
__device__ __forceinline__ float gelu_f(float v) {
    float x = fabsf(v) * 0.7071067811865475f;
    float t = __fdividef(1.0f, fmaf(0.3275911f, x, 1.0f));
    float p = t * fmaf(t, fmaf(t, fmaf(t, fmaf(t, 1.061405429f, -1.453152027f),
                 1.421413741f), -0.284496736f), 0.254829592f);
    float erfax = 1.0f - p * __expf(-x * x);
    float erfv = copysignf(erfax, v);
    return 0.5f * v * (1.0f + erfv);
}
__device__ __forceinline__ u64 gelu2(u64 v) {
    float a, b; upk(v, a, b);
    return pk(gelu_f(a), gelu_f(b));
}

// ---------------- tables (exact mod-256 angle reduction) ----------------
__global__ void k_tables() {
    int k = blockIdx.x;          // 0..15
    int y = threadIdx.x;         // 0..255
    int p = (k * y) & 255;
    float ang = (float)p * 0.024543692606170259f;  // 2*pi/256
    float s, c;
    sincosf(ang, &s, &c);
    g_ctab[k*NPTS+y] = c;   g_stab[k*NPTS+y] = s;
    g_ctT[y*MODES+k] = c;   g_stT[y*MODES+k] = s;
}

// ---------------- repack spectral weights [l][i][o][kx][ky] -> [l][ky][kx][i][o] ----------------
__global__ void k_repack(const float* __restrict__ wr, const float* __restrict__ wi) {
    int blk = blockIdx.x;          // 0..127 = l*32 + i
    int l = blk >> 5, i = blk & 31;
    const float* wrb = wr + (size_t)blk * CH * MODES * MODES;
    const float* wib = wi + (size_t)blk * CH * MODES * MODES;
    for (int idx = threadIdx.x; idx < MODES*MODES*CH; idx += blockDim.x) {
        int o  = idx & 31;
        int kx = (idx >> 5) & 15;
        int ky = idx >> 9;
        int s  = o*(MODES*MODES) + kx*MODES + ky;
        g_Wp[(((size_t)(l*MODES+ky)*MODES+kx)*CH + i)*CH + o] = make_float2(wrb[s], wib[s]);
    }
}

// ---------------- lifting: (bc,x,y) -> h[b][c][x][y] ----------------
__global__ void k_lift(const float* __restrict__ bc, const float* __restrict__ xin,
                       const float* __restrict__ yin, const float* __restrict__ mw,
                       const float* __restrict__ mb) {
    int blk = blockIdx.x;                 // b*256 + xi
    int b = blk >> 8, xi = blk & 255;
    int y = threadIdx.x;                  // 256
    float b0 = bc[b*3+0], b1 = bc[b*3+1], b2 = bc[b*3+2];
    float xv = xin[(b*NPTS+xi)*NPTS + y];
    float yv = yin[(b*NPTS+xi)*NPTS + y];
    #pragma unroll
    for (int c = 0; c < CH; c++) {
        float h = mb[c] + b0*mw[c] + b1*mw[32+c] + b2*mw[64+c] + xv*mw[96+c] + yv*mw[128+c];
        g_h[((size_t)(b*CH+c)*NPTS + xi)*NPTS + y] = h;
    }
}

// ---------------- forward y-DFT: h -> A (16 complex modes) ----------------
// block = (bcIdx, x-tile of 32); 128 threads = 16 ky * 8 xg; 4 rows/thread
// packed over y-pairs: acc_re2 += (h[y],h[y+1]) * (c[y],c[y+1]) etc.
__global__ __launch_bounds__(128) void k_fwd() {
    __shared__ __align__(16) float cs[MODES*NPTS];   // 16 KB [k][y]
    __shared__ __align__(16) float sn[MODES*NPTS];   // 16 KB
    int tid = threadIdx.x;
    int blk = blockIdx.x;               // bcIdx*8 + xt
    int xt = blk & 7;
    int bcIdx = blk >> 3;               // b*32+c

    {
        const float4* c4 = (const float4*)g_ctab;
        const float4* s4 = (const float4*)g_stab;
        float4* cd = (float4*)cs; float4* sd = (float4*)sn;
        #pragma unroll
        for (int i = tid; i < 1024; i += 128) { cd[i] = c4[i]; sd[i] = s4[i]; }
    }
    __syncthreads();

    int ky = tid & 15, xg = tid >> 4;   // 16 ky, 8 xg
    int x0 = xt*32 + xg*4;
    const float4* h4 = (const float4*)(g_h + ((size_t)bcIdx*NPTS + x0)*NPTS);
    const u64* cp = (const u64*)(cs + ky*NPTS);
    const u64* sp = (const u64*)(sn + ky*NPTS);

    u64 ar[4] = {0,0,0,0}, ai[4] = {0,0,0,0};
    #pragma unroll 4
    for (int yq = 0; yq < 64; yq++) {
        u64 c0 = cp[2*yq], c1 = cp[2*yq+1];
        u64 s0 = sp[2*yq], s1 = sp[2*yq+1];
        #pragma unroll
        for (int r = 0; r < 4; r++) {
            float4 v = h4[r*64 + yq];
            u64 hlo = pk(v.x, v.y), hhi = pk(v.z, v.w);
            ar[r] = fma2(hlo, c0, ar[r]);
            ar[r] = fma2(hhi, c1, ar[r]);
            ai[r] = fma2(hlo, s0, ai[r]);
            ai[r] = fma2(hhi, s1, ai[r]);
        }
    }
    int b = bcIdx >> 5, c = bcIdx & 31;
    float2* outp = g_A + ((size_t)(b*MODES+ky)*CH + c)*NPTS + x0;
    #pragma unroll
    for (int r = 0; r < 4; r++) {
        float rl, rh, il, ih;
        upk(ar[r], rl, rh); upk(ai[r], il, ih);
        outp[r] = make_float2(rl + rh, -(il + ih));   // e^{-i...}: im = -sum h*sin
    }
}

// ---------------- x-DFT + mode mixing + inverse x-DFT ----------------
// block = (b, ky): 128 blocks, 512 threads
__global__ __launch_bounds__(512) void k_spec(int layer) {
    __shared__ float2 Hft[CH*MODES];     //  4 KB [i][kx]
    __shared__ float  Tmr[CH*17];        // padded [o][kx]
    __shared__ float  Tmi[CH*17];
    int tid = threadIdx.x;               // 512
    int b = blockIdx.x >> 4, ky = blockIdx.x & 15;

    // forward x-DFT: Hft[c][kx] = (1/256) * sum_x A[c][x] * e^{-i 2pi kx x/256}
    {
        int c = tid >> 4, kx = tid & 15;
        const float2* Arow = g_A + ((size_t)(b*MODES+ky)*CH + c)*NPTS;
        float ar = 0.f, ai = 0.f;
        #pragma unroll 4
        for (int x = 0; x < 256; x++) {
            float2 a = Arow[x];
            float cc = g_ctT[x*16+kx], sv = g_stT[x*16+kx];
            ar += a.x*cc + a.y*sv;
            ai += a.y*cc - a.x*sv;
        }
        Hft[c*16+kx] = make_float2(ar*(1.0f/256.0f), ai*(1.0f/256.0f));
    }
    __syncthreads();

    // mode mixing: T[o][kx] = sum_i Hft[i][kx] * (wr + i*wi)[i][o]
    {
        int kx = tid >> 5, o = tid & 31;
        const float2* W = g_Wp + ((size_t)((layer*MODES+ky)*MODES + kx)*CH)*CH;
        float tr = 0.f, ti = 0.f;
        #pragma unroll 8
        for (int i = 0; i < CH; i++) {
            float2 hh = Hft[i*16+kx];
            float2 w = W[i*32+o];
            tr += hh.x*w.x - hh.y*w.y;
            ti += hh.x*w.y + hh.y*w.x;
        }
        Tmr[o*17+kx] = tr;
        Tmi[o*17+kx] = ti;
    }
    __syncthreads();

    // inverse x-DFT (hermitian-y doubling + inverse 1/256 folded in):
    {
        int xg = tid >> 5, o = tid & 31;
        float Tr[16], Ti[16];
        #pragma unroll
        for (int k = 0; k < 16; k++) { Tr[k] = Tmr[o*17+k]; Ti[k] = Tmi[o*17+k]; }
        float scale = (ky == 0) ? (1.0f/256.0f) : (2.0f/256.0f);
        for (int j = 0; j < 16; j++) {
            int x = xg*16 + j;
            float br = 0.f, bi = 0.f;
            #pragma unroll
            for (int k = 0; k < 16; k++) {
                float cc = g_ctT[x*16+k], sv = g_stT[x*16+k];
                br += Tr[k]*cc - Ti[k]*sv;
                bi += Tr[k]*sv + Ti[k]*cc;
            }
            g_T2[((size_t)(b*NPTS+x)*MODES + ky)*CH + o] = make_float2(br*scale, bi*scale);
        }
    }
}

// ---------------- combine: h = h + gelu(inv-y-DFT(T2) + pointwise(h) + bias) ----------------
// block = (b, x), 256 threads (thread = y); packed over output-channel pairs
__global__ __launch_bounds__(256) void k_layer(const float* __restrict__ pww,
                                               const float* __restrict__ pwb, int layer) {
    __shared__ __align__(16) float T2r[MODES*CH];   // [k][o], 2 KB
    __shared__ __align__(16) float T2i[MODES*CH];   // 2 KB
    __shared__ __align__(16) float wsP[CH*CH];      // transposed [i][o], 4 KB
    __shared__ __align__(8)  float pbs[CH];
    int tid = threadIdx.x;             // 256
    int b = blockIdx.x >> 8, x = blockIdx.x & 255;

    {   // stage + deinterleave T2
        const float2* src = g_T2 + (size_t)(b*NPTS + x)*MODES*CH;
        float2 v0 = src[tid];        T2r[tid] = v0.x;        T2i[tid] = v0.y;
        float2 v1 = src[tid + 256];  T2r[tid + 256] = v1.x;  T2i[tid + 256] = v1.y;
    }
    {   // stage transposed pointwise weights: wsP[i][o] = pww[l][o][i]
        for (int idx = tid; idx < CH*CH; idx += 256) {
            int o = idx >> 5, i = idx & 31;
            wsP[i*32 + o] = pww[layer*CH*CH + idx];
        }
        if (tid < CH) pbs[tid] = pwb[layer*CH + tid];
    }

    int y = tid;
    float hreg[CH];
    #pragma unroll
    for (int i = 0; i < CH; i++) hreg[i] = g_h[((size_t)(b*CH+i)*NPTS + x)*NPTS + y];
    __syncthreads();

    // 16 packed accumulators: acc[p] holds outputs (2p, 2p+1)
    u64 acc[16];
    #pragma unroll
    for (int p = 0; p < 16; p++) acc[p] = *(const u64*)&pbs[2*p];

    // pointwise: acc += (h_i,h_i) * (w[i][o],w[i][o+1])
    #pragma unroll 4
    for (int i = 0; i < CH; i++) {
        u64 hd = pk(hreg[i], hreg[i]);
        #pragma unroll
        for (int q = 0; q < 8; q++) {
            u64x2 w = *(const u64x2*)&wsP[i*32 + 4*q];
            acc[2*q]   = fma2(hd, w.x, acc[2*q]);
            acc[2*q+1] = fma2(hd, w.y, acc[2*q+1]);
        }
    }
    // inverse y-DFT: acc += cr*T2r + (-sn)*T2i
    #pragma unroll 2
    for (int k = 0; k < 16; k++) {
        float cv = g_ctab[k*NPTS + y];
        float sv = g_stab[k*NPTS + y];
        u64 cd = pk(cv, cv);
        u64 sd = pk(-sv, -sv);
        #pragma unroll
        for (int q = 0; q < 8; q++) {
            u64x2 tr = *(const u64x2*)&T2r[k*32 + 4*q];
            u64x2 ti = *(const u64x2*)&T2i[k*32 + 4*q];
            acc[2*q]   = fma2(cd, tr.x, acc[2*q]);
            acc[2*q+1] = fma2(cd, tr.y, acc[2*q+1]);
            acc[2*q]   = fma2(sd, ti.x, acc[2*q]);
            acc[2*q+1] = fma2(sd, ti.y, acc[2*q+1]);
        }
    }
    // epilogue: gelu + residual + store
    #pragma unroll
    for (int p = 0; p < 16; p++) {
        float a0, a1; upk(acc[p], a0, a1);
        int o = 2*p;
        g_h[((size_t)(b*CH+o  )*NPTS + x)*NPTS + y] = hreg[o]   + gelu_f(a0);
        g_h[((size_t)(b*CH+o+1)*NPTS + x)*NPTS + y] = hreg[o+1] + gelu_f(a1);
    }
}

// ---------------- decoders: 3x (32 -> 32 -> 128 -> 1), 2 points/thread ----------------
__global__ __launch_bounds__(128) void k_dec(
        const float* __restrict__ w1, const float* __restrict__ b1,
        const float* __restrict__ w2, const float* __restrict__ b2,
        const float* __restrict__ w3, const float* __restrict__ b3,
        float* __restrict__ out) {
    __shared__ __align__(16) u64 W1d[CH*CH];     // dup-packed [i][j],  8 KB
    __shared__ __align__(16) u64 W2d[CH*HID];    // dup-packed [i][j], 32 KB
    __shared__ __align__(16) u64 W3d[HID];       //  1 KB
    __shared__ __align__(16) u64 B1d[CH];
    __shared__ __align__(16) u64 B2d[HID];
    int tid = threadIdx.x;           // 128
    int b = blockIdx.x >> 8, x = blockIdx.x & 255;
    int y0 = 2*tid;                  // this thread: points (y0, y0+1)

    // load h pairs: naturally packed via LDG.64
    u64 hd[CH];
    #pragma unroll
    for (int i = 0; i < CH; i++)
        hd[i] = *(const u64*)(g_h + ((size_t)(b*CH+i)*NPTS + x)*NPTS + y0);

    for (int d = 0; d < 3; d++) {
        __syncthreads();
        for (int idx = tid; idx < CH*CH; idx += 128) {
            float w = w1[d*CH*CH + idx]; W1d[idx] = pk(w, w);
        }
        for (int idx = tid; idx < CH*HID; idx += 128) {
            float w = w2[d*CH*HID + idx]; W2d[idx] = pk(w, w);
        }
        if (tid < HID) {
            float w = w3[d*HID + tid]; W3d[tid] = pk(w, w);
            float bb = b2[d*HID + tid]; B2d[tid] = pk(bb, bb);
        }
        if (tid < CH) { float bb = b1[d*CH + tid]; B1d[tid] = pk(bb, bb); }
        __syncthreads();

        // stage 1: z1[j] = gelu(b1[j] + sum_i h[i] * w1[i][j])
        u64 z1[CH];
        #pragma unroll 2
        for (int jp = 0; jp < CH/2; jp++) {
            u64 a0 = B1d[2*jp], a1 = B1d[2*jp+1];
            #pragma unroll
            for (int i = 0; i < CH; i++) {
                u64x2 w = *(const u64x2*)&W1d[i*CH + 2*jp];
                a0 = fma2(hd[i], w.x, a0);
                a1 = fma2(hd[i], w.y, a1);
            }
            z1[2*jp]   = gelu2(a0);
            z1[2*jp+1] = gelu2(a1);
        }
        // stage 2+3: o = b3 + sum_j w3[j] * gelu(b2[j] + sum_i z1[i] * w2[i][j])
        u64 o2 = 0;
        for (int jp = 0; jp < HID/2; jp++) {
            u64 a0 = B2d[2*jp], a1 = B2d[2*jp+1];
            #pragma unroll
            for (int i = 0; i < CH; i++) {
                u64x2 w = *(const u64x2*)&W2d[i*HID + 2*jp];
                a0 = fma2(z1[i], w.x, a0);
                a1 = fma2(z1[i], w.y, a1);
            }
            o2 = fma2(gelu2(a0), W3d[2*jp],   o2);
            o2 = fma2(gelu2(a1), W3d[2*jp+1], o2);
        }
        float r0, r1; upk(o2, r0, r1);
        float bias3 = b3[d];
        size_t p = ((size_t)(b*NPTS + x))*NPTS + y0;
        out[p*3 + d]     = r0 + bias3;
        out[(p+1)*3 + d] = r1 + bias3;
    }
}

extern "C" void kernel_launch(void* const* d_in, const int* in_sizes, int n_in,
                              void* d_out, int out_size) {
    const float* bc      = (const float*)d_in[0];
    const float* xin     = (const float*)d_in[1];
    const float* yin     = (const float*)d_in[2];
    const float* mlp1_w  = (const float*)d_in[3];
    const float* mlp1_b  = (const float*)d_in[4];
    const float* spec_wr = (const float*)d_in[5];
    const float* spec_wi = (const float*)d_in[6];
    const float* pw_w    = (const float*)d_in[7];
    const float* pw_b    = (const float*)d_in[8];
    const float* dec_w1  = (const float*)d_in[9];
    const float* dec_b1  = (const float*)d_in[10];
    const float* dec_w2  = (const float*)d_in[11];
    const float* dec_b2  = (const float*)d_in[12];
    const float* dec_w3  = (const float*)d_in[13];
    const float* dec_b3  = (const float*)d_in[14];
    float* out = (float*)d_out;

    k_tables<<<16, 256>>>();
    k_repack<<<NLAY*CH, 256>>>(spec_wr, spec_wi);
    k_lift<<<BATCH*NPTS, 256>>>(bc, xin, yin, mlp1_w, mlp1_b);
    for (int l = 0; l < NLAY; l++) {
        k_fwd<<<BATCH*CH*8, 128>>>();
        k_spec<<<BATCH*MODES, 512>>>(l);
        k_layer<<<BATCH*NPTS, 256>>>(pw_w, pw_b, l);
    }
    k_dec<<<BATCH*NPTS, 128>>>(dec_w1, dec_b1, dec_w2, dec_b2, dec_w3, dec_b3, out);
}

// round 5
// speedup vs baseline: 1.3338x; 1.3202x over previous
#include <cuda_runtime.h>
#include <math.h>

#define BATCH 8
#define NPTS  256
#define CH    32
#define MODES 16
#define NLAY  4
#define HID   128

typedef unsigned long long u64;
typedef ulonglong2 u64x2;

// ---------------- packed f32x2 helpers (sm_100+) ----------------
__device__ __forceinline__ u64 pk(float lo, float hi) {
    u64 r; asm("mov.b64 %0, {%1, %2};" : "=l"(r) : "f"(lo), "f"(hi)); return r;
}
__device__ __forceinline__ void upk(u64 v, float& lo, float& hi) {
    asm("mov.b64 {%0, %1}, %2;" : "=f"(lo), "=f"(hi) : "l"(v));
}
__device__ __forceinline__ u64 fma2(u64 a, u64 b, u64 c) {
    u64 d; asm("fma.rn.f32x2 %0, %1, %2, %3;" : "=l"(d) : "l"(a), "l"(b), "l"(c)); return d;
}
__device__ __forceinline__ u64 mul2(u64 a, u64 b) { return fma2(a, b, 0ULL); }

// ---------------- scratch (static device globals; no allocations) ----------------
__device__ float  g_h[BATCH*CH*NPTS*NPTS];          // 64 MB, [b][c][x][y]
__device__ float2 g_A[BATCH*MODES*CH*NPTS];         // fwd y-DFT, [b][ky][c][x]
__device__ float2 g_T2[BATCH*NPTS*MODES*CH];        // after inv x-DFT, [b][x][ky][o]
__device__ float2 g_Wp[NLAY*MODES*MODES*CH*CH];     // repacked spec weights [l][ky][kx][i][o]
__device__ float  g_ctab[MODES*NPTS];               // cos(2*pi*k*y/256)  [k][y]
__device__ float  g_stab[MODES*NPTS];               // sin                [k][y]
__device__ float  g_ctT[NPTS*MODES];                // transposed [x][k]
__device__ float  g_stT[NPTS*MODES];
__device__ float4 g_tabP[MODES*128];                // [k][j]: (c2j, c2j+1, s2j, s2j+1)

// Branch-free erf-based GELU (Abramowitz-Stegun 7.1.26, |err| < 2e-7)
__device__ __forceinline__ float gelu_f(float v) {
    float x = fabsf(v) * 0.7071067811865475f;
    float t = __fdividef(1.0f, fmaf(0.3275911f, x, 1.0f));
    float p = t * fmaf(t, fmaf(t, fmaf(t, fmaf(t, 1.061405429f, -1.453152027f),
                 1.421413741f), -0.284496736f), 0.254829592f);
    float erfax = 1.0f - p * __expf(-x * x);
    float erfv = copysignf(erfax, v);
    return 0.5f * v * (1.0f + erfv);
}

// Packed GELU on a float pair: polynomial + epilogue in f32x2, rcp/exp scalar
__device__ __forceinline__ u64 gelu2(u64 v) {
    float v0, v1; upk(v, v0, v1);
    float x0 = fabsf(v0) * 0.7071067811865475f;
    float x1 = fabsf(v1) * 0.7071067811865475f;
    float t0 = __fdividef(1.0f, fmaf(0.3275911f, x0, 1.0f));
    float t1 = __fdividef(1.0f, fmaf(0.3275911f, x1, 1.0f));
    float e0 = -__expf(x0 * -x0);
    float e1 = -__expf(x1 * -x1);
    u64 t = pk(t0, t1);
    u64 p = fma2(t, pk(1.061405429f, 1.061405429f), pk(-1.453152027f, -1.453152027f));
    p = fma2(p, t, pk(1.421413741f, 1.421413741f));
    p = fma2(p, t, pk(-0.284496736f, -0.284496736f));
    p = fma2(p, t, pk(0.254829592f, 0.254829592f));
    p = mul2(p, t);
    u64 er = fma2(p, pk(e0, e1), pk(1.0f, 1.0f));   // 1 - p*exp(-x^2), in [0,1]
    er |= (v & 0x8000000080000000ULL);              // copysign from v
    u64 u = fma2(er, pk(0.5f, 0.5f), pk(0.5f, 0.5f));
    return mul2(v, u);
}

// ---------------- tables (exact mod-256 angle reduction) ----------------
__global__ void k_tables() {
    int k = blockIdx.x;          // 0..15
    int y = threadIdx.x;         // 0..255
    int p = (k * y) & 255;
    float ang = (float)p * 0.024543692606170259f;  // 2*pi/256
    float s, c;
    sincosf(ang, &s, &c);
    g_ctab[k*NPTS+y] = c;   g_stab[k*NPTS+y] = s;
    g_ctT[y*MODES+k] = c;   g_stT[y*MODES+k] = s;
    float* tp = (float*)&g_tabP[k*128 + (y >> 1)];
    tp[y & 1] = c;
    tp[2 + (y & 1)] = s;
}

// ---------------- repack spectral weights [l][i][o][kx][ky] -> [l][ky][kx][i][o] ----------------
__global__ void k_repack(const float* __restrict__ wr, const float* __restrict__ wi) {
    int blk = blockIdx.x;          // 0..127 = l*32 + i
    int l = blk >> 5, i = blk & 31;
    const float* wrb = wr + (size_t)blk * CH * MODES * MODES;
    const float* wib = wi + (size_t)blk * CH * MODES * MODES;
    for (int idx = threadIdx.x; idx < MODES*MODES*CH; idx += blockDim.x) {
        int o  = idx & 31;
        int kx = (idx >> 5) & 15;
        int ky = idx >> 9;
        int s  = o*(MODES*MODES) + kx*MODES + ky;
        g_Wp[(((size_t)(l*MODES+ky)*MODES+kx)*CH + i)*CH + o] = make_float2(wrb[s], wib[s]);
    }
}

// ---------------- lifting: (bc,x,y) -> h[b][c][x][y] ----------------
__global__ void k_lift(const float* __restrict__ bc, const float* __restrict__ xin,
                       const float* __restrict__ yin, const float* __restrict__ mw,
                       const float* __restrict__ mb) {
    int blk = blockIdx.x;                 // b*256 + xi
    int b = blk >> 8, xi = blk & 255;
    int y = threadIdx.x;                  // 256
    float b0 = bc[b*3+0], b1 = bc[b*3+1], b2 = bc[b*3+2];
    float xv = xin[(b*NPTS+xi)*NPTS + y];
    float yv = yin[(b*NPTS+xi)*NPTS + y];
    #pragma unroll
    for (int c = 0; c < CH; c++) {
        float h = mb[c] + b0*mw[c] + b1*mw[32+c] + b2*mw[64+c] + xv*mw[96+c] + yv*mw[128+c];
        g_h[((size_t)(b*CH+c)*NPTS + xi)*NPTS + y] = h;
    }
}

// ---------------- forward y-DFT: h -> A (16 complex modes) ----------------
// block = (bcIdx, x-tile of 32); 128 threads = 16 ky * 8 xg; 4 rows/thread
// table staged interleaved (c,c,s,s) with row stride 129 float4 -> conflict-free LDS.128
__global__ __launch_bounds__(128) void k_fwd() {
    __shared__ __align__(16) float4 tab4[MODES*129];   // ~33 KB
    int tid = threadIdx.x;
    int blk = blockIdx.x;               // bcIdx*8 + xt
    int xt = blk & 7;
    int bcIdx = blk >> 3;               // b*32+c

    #pragma unroll
    for (int it = 0; it < 16; it++) {
        int i = it*128 + tid;
        tab4[(i >> 7)*129 + (i & 127)] = g_tabP[i];
    }
    __syncthreads();

    int ky = tid & 15, xg = tid >> 4;   // 16 ky, 8 xg
    int x0 = xt*32 + xg*4;
    const u64x2* h2 = (const u64x2*)(g_h + ((size_t)bcIdx*NPTS + x0)*NPTS);
    const u64x2* tp = (const u64x2*)(tab4 + ky*129);

    u64 ar[4] = {0,0,0,0}, ai[4] = {0,0,0,0};
    #pragma unroll 4
    for (int j2 = 0; j2 < 64; j2++) {
        u64x2 t0 = tp[2*j2];        // (c,c),(s,s) for y-pair 2*j2
        u64x2 t1 = tp[2*j2+1];      // y-pair 2*j2+1
        #pragma unroll
        for (int r = 0; r < 4; r++) {
            u64x2 hv = h2[r*64 + j2];   // y 4*j2 .. 4*j2+3
            ar[r] = fma2(hv.x, t0.x, ar[r]);
            ai[r] = fma2(hv.x, t0.y, ai[r]);
            ar[r] = fma2(hv.y, t1.x, ar[r]);
            ai[r] = fma2(hv.y, t1.y, ai[r]);
        }
    }
    int b = bcIdx >> 5, c = bcIdx & 31;
    float2* outp = g_A + ((size_t)(b*MODES+ky)*CH + c)*NPTS + x0;
    #pragma unroll
    for (int r = 0; r < 4; r++) {
        float rl, rh, il, ih;
        upk(ar[r], rl, rh); upk(ai[r], il, ih);
        outp[r] = make_float2(rl + rh, -(il + ih));   // e^{-i...}: im = -sum h*sin
    }
}

// ---------------- x-DFT + mode mixing + inverse x-DFT ----------------
// block = (b, ky): 128 blocks, 512 threads
__global__ __launch_bounds__(512) void k_spec(int layer) {
    __shared__ float2 Hft[CH*MODES];     //  4 KB [i][kx]
    __shared__ float  Tmr[CH*17];        // padded [o][kx]
    __shared__ float  Tmi[CH*17];
    int tid = threadIdx.x;               // 512
    int b = blockIdx.x >> 4, ky = blockIdx.x & 15;

    // forward x-DFT: Hft[c][kx] = (1/256) * sum_x A[c][x] * e^{-i 2pi kx x/256}
    {
        int c = tid >> 4, kx = tid & 15;
        const float2* Arow = g_A + ((size_t)(b*MODES+ky)*CH + c)*NPTS;
        float ar = 0.f, ai = 0.f;
        #pragma unroll 4
        for (int x = 0; x < 256; x++) {
            float2 a = Arow[x];
            float cc = g_ctT[x*16+kx], sv = g_stT[x*16+kx];
            ar += a.x*cc + a.y*sv;
            ai += a.y*cc - a.x*sv;
        }
        Hft[c*16+kx] = make_float2(ar*(1.0f/256.0f), ai*(1.0f/256.0f));
    }
    __syncthreads();

    // mode mixing: T[o][kx] = sum_i Hft[i][kx] * (wr + i*wi)[i][o]
    {
        int kx = tid >> 5, o = tid & 31;
        const float2* W = g_Wp + ((size_t)((layer*MODES+ky)*MODES + kx)*CH)*CH;
        float tr = 0.f, ti = 0.f;
        #pragma unroll 8
        for (int i = 0; i < CH; i++) {
            float2 hh = Hft[i*16+kx];
            float2 w = W[i*32+o];
            tr += hh.x*w.x - hh.y*w.y;
            ti += hh.x*w.y + hh.y*w.x;
        }
        Tmr[o*17+kx] = tr;
        Tmi[o*17+kx] = ti;
    }
    __syncthreads();

    // inverse x-DFT (hermitian-y doubling + inverse 1/256 folded in)
    {
        int xg = tid >> 5, o = tid & 31;
        float Tr[16], Ti[16];
        #pragma unroll
        for (int k = 0; k < 16; k++) { Tr[k] = Tmr[o*17+k]; Ti[k] = Tmi[o*17+k]; }
        float scale = (ky == 0) ? (1.0f/256.0f) : (2.0f/256.0f);
        for (int j = 0; j < 16; j++) {
            int x = xg*16 + j;
            float br = 0.f, bi = 0.f;
            #pragma unroll
            for (int k = 0; k < 16; k++) {
                float cc = g_ctT[x*16+k], sv = g_stT[x*16+k];
                br += Tr[k]*cc - Ti[k]*sv;
                bi += Tr[k]*sv + Ti[k]*cc;
            }
            g_T2[((size_t)(b*NPTS+x)*MODES + ky)*CH + o] = make_float2(br*scale, bi*scale);
        }
    }
}

// ---------------- combine: h = h + gelu(inv-y-DFT(T2) + pointwise(h) + bias) ----------------
// block = (b, x), 256 threads (thread = y); packed over output-channel pairs
__global__ __launch_bounds__(256) void k_layer(const float* __restrict__ pww,
                                               const float* __restrict__ pwb, int layer) {
    __shared__ __align__(16) float T2r[MODES*CH];   // [k][o], 2 KB
    __shared__ __align__(16) float T2i[MODES*CH];   // 2 KB
    __shared__ __align__(16) float wsP[CH*CH];      // transposed [i][o], 4 KB
    __shared__ __align__(8)  float pbs[CH];
    int tid = threadIdx.x;             // 256
    int b = blockIdx.x >> 8, x = blockIdx.x & 255;

    {   // stage + deinterleave T2
        const float2* src = g_T2 + (size_t)(b*NPTS + x)*MODES*CH;
        float2 v0 = src[tid];        T2r[tid] = v0.x;        T2i[tid] = v0.y;
        float2 v1 = src[tid + 256];  T2r[tid + 256] = v1.x;  T2i[tid + 256] = v1.y;
    }
    {   // stage transposed pointwise weights: wsP[i][o] = pww[l][o][i]
        for (int idx = tid; idx < CH*CH; idx += 256) {
            int o = idx >> 5, i = idx & 31;
            wsP[i*32 + o] = pww[layer*CH*CH + idx];
        }
        if (tid < CH) pbs[tid] = pwb[layer*CH + tid];
    }

    int y = tid;
    float hreg[CH];
    #pragma unroll
    for (int i = 0; i < CH; i++) hreg[i] = g_h[((size_t)(b*CH+i)*NPTS + x)*NPTS + y];
    __syncthreads();

    // 16 packed accumulators: acc[p] holds outputs (2p, 2p+1)
    u64 acc[16];
    #pragma unroll
    for (int p = 0; p < 16; p++) acc[p] = *(const u64*)&pbs[2*p];

    // pointwise: acc += (h_i,h_i) * (w[i][o],w[i][o+1])
    #pragma unroll 4
    for (int i = 0; i < CH; i++) {
        u64 hd = pk(hreg[i], hreg[i]);
        #pragma unroll
        for (int q = 0; q < 8; q++) {
            u64x2 w = *(const u64x2*)&wsP[i*32 + 4*q];
            acc[2*q]   = fma2(hd, w.x, acc[2*q]);
            acc[2*q+1] = fma2(hd, w.y, acc[2*q+1]);
        }
    }
    // inverse y-DFT: acc += cr*T2r + (-sn)*T2i
    #pragma unroll 2
    for (int k = 0; k < 16; k++) {
        float cv = g_ctab[k*NPTS + y];
        float sv = g_stab[k*NPTS + y];
        u64 cd = pk(cv, cv);
        u64 sd = pk(-sv, -sv);
        #pragma unroll
        for (int q = 0; q < 8; q++) {
            u64x2 tr = *(const u64x2*)&T2r[k*32 + 4*q];
            u64x2 ti = *(const u64x2*)&T2i[k*32 + 4*q];
            acc[2*q]   = fma2(cd, tr.x, acc[2*q]);
            acc[2*q+1] = fma2(cd, tr.y, acc[2*q+1]);
            acc[2*q]   = fma2(sd, ti.x, acc[2*q]);
            acc[2*q+1] = fma2(sd, ti.y, acc[2*q+1]);
        }
    }
    // epilogue: packed gelu + residual + store
    #pragma unroll
    for (int p = 0; p < 16; p++) {
        float g0, g1; upk(gelu2(acc[p]), g0, g1);
        int o = 2*p;
        g_h[((size_t)(b*CH+o  )*NPTS + x)*NPTS + y] = hreg[o]   + g0;
        g_h[((size_t)(b*CH+o+1)*NPTS + x)*NPTS + y] = hreg[o+1] + g1;
    }
}

// ---------------- decoders: 3x (32 -> 32 -> 128 -> 1), 2 points/thread ----------------
__global__ __launch_bounds__(128) void k_dec(
        const float* __restrict__ w1, const float* __restrict__ b1,
        const float* __restrict__ w2, const float* __restrict__ b2,
        const float* __restrict__ w3, const float* __restrict__ b3,
        float* __restrict__ out) {
    __shared__ __align__(16) u64 W1d[CH*CH];     // dup-packed [i][j],  8 KB
    __shared__ __align__(16) u64 W2d[CH*HID];    // dup-packed [i][j], 32 KB
    __shared__ __align__(16) u64 W3d[HID];       //  1 KB
    __shared__ __align__(16) u64 B1d[CH];
    __shared__ __align__(16) u64 B2d[HID];
    int tid = threadIdx.x;           // 128
    int b = blockIdx.x >> 8, x = blockIdx.x & 255;
    int y0 = 2*tid;                  // this thread: points (y0, y0+1)

    // load h pairs: naturally packed via LDG.64
    u64 hd[CH];
    #pragma unroll
    for (int i = 0; i < CH; i++)
        hd[i] = *(const u64*)(g_h + ((size_t)(b*CH+i)*NPTS + x)*NPTS + y0);

    for (int d = 0; d < 3; d++) {
        __syncthreads();
        for (int idx = tid; idx < CH*CH; idx += 128) {
            float w = w1[d*CH*CH + idx]; W1d[idx] = pk(w, w);
        }
        for (int idx = tid; idx < CH*HID; idx += 128) {
            float w = w2[d*CH*HID + idx]; W2d[idx] = pk(w, w);
        }
        if (tid < HID) {
            float w = w3[d*HID + tid]; W3d[tid] = pk(w, w);
            float bb = b2[d*HID + tid]; B2d[tid] = pk(bb, bb);
        }
        if (tid < CH) { float bb = b1[d*CH + tid]; B1d[tid] = pk(bb, bb); }
        __syncthreads();

        // stage 1: z1[j] = gelu(b1[j] + sum_i h[i] * w1[i][j])
        u64 z1[CH];
        #pragma unroll 2
        for (int jp = 0; jp < CH/2; jp++) {
            u64 a0 = B1d[2*jp], a1 = B1d[2*jp+1];
            #pragma unroll
            for (int i = 0; i < CH; i++) {
                u64x2 w = *(const u64x2*)&W1d[i*CH + 2*jp];
                a0 = fma2(hd[i], w.x, a0);
                a1 = fma2(hd[i], w.y, a1);
            }
            z1[2*jp]   = gelu2(a0);
            z1[2*jp+1] = gelu2(a1);
        }
        // stage 2+3: o = b3 + sum_j w3[j] * gelu(b2[j] + sum_i z1[i] * w2[i][j])
        u64 o2 = 0;
        #pragma unroll 2
        for (int jp = 0; jp < HID/2; jp++) {
            u64 a0 = B2d[2*jp], a1 = B2d[2*jp+1];
            #pragma unroll
            for (int i = 0; i < CH; i++) {
                u64x2 w = *(const u64x2*)&W2d[i*HID + 2*jp];
                a0 = fma2(z1[i], w.x, a0);
                a1 = fma2(z1[i], w.y, a1);
            }
            o2 = fma2(gelu2(a0), W3d[2*jp],   o2);
            o2 = fma2(gelu2(a1), W3d[2*jp+1], o2);
        }
        float r0, r1; upk(o2, r0, r1);
        float bias3 = b3[d];
        size_t p = ((size_t)(b*NPTS + x))*NPTS + y0;
        out[p*3 + d]     = r0 + bias3;
        out[(p+1)*3 + d] = r1 + bias3;
    }
}

extern "C" void kernel_launch(void* const* d_in, const int* in_sizes, int n_in,
                              void* d_out, int out_size) {
    const float* bc      = (const float*)d_in[0];
    const float* xin     = (const float*)d_in[1];
    const float* yin     = (const float*)d_in[2];
    const float* mlp1_w  = (const float*)d_in[3];
    const float* mlp1_b  = (const float*)d_in[4];
    const float* spec_wr = (const float*)d_in[5];
    const float* spec_wi = (const float*)d_in[6];
    const float* pw_w    = (const float*)d_in[7];
    const float* pw_b    = (const float*)d_in[8];
    const float* dec_w1  = (const float*)d_in[9];
    const float* dec_b1  = (const float*)d_in[10];
    const float* dec_w2  = (const float*)d_in[11];
    const float* dec_b2  = (const float*)d_in[12];
    const float* dec_w3  = (const float*)d_in[13];
    const float* dec_b3  = (const float*)d_in[14];
    float* out = (float*)d_out;

    k_tables<<<16, 256>>>();
    k_repack<<<NLAY*CH, 256>>>(spec_wr, spec_wi);
    k_lift<<<BATCH*NPTS, 256>>>(bc, xin, yin, mlp1_w, mlp1_b);
    for (int l = 0; l < NLAY; l++) {
        k_fwd<<<BATCH*CH*8, 128>>>();
        k_spec<<<BATCH*MODES, 512>>>(l);
        k_layer<<<BATCH*NPTS, 256>>>(pw_w, pw_b, l);
    }
    k_dec<<<BATCH*NPTS, 128>>>(dec_w1, dec_b1, dec_w2, dec_b2, dec_w3, dec_b3, out);
}